// round 15
// baseline (speedup 1.0000x reference)
#include <cuda_runtime.h>
#include <cstdint>

// ---------------------------------------------------------------------------
// Gcs_loss, expanded form:
//   v = pred - truth, halves X = v[:,:P], Y = v[:,P:]
//   s_i = S2 - 2 * dot_i + P * colsq_i,
//   dot_i = sum_b v[b,i]*rowsum[b],  colsq_i = sum_b v[b,i]^2
//   out = ( sum_i sqrt(s_i^X) + sum_i sqrt(s_i^Y) ) / (2B),  B=32, P=1024.
//
// ONE cluster of 8 CTAs, 512 threads (16 warps); CTA r owns column slice r
// (128 cols) of BOTH halves; warp w loads rows 2w, 2w+1.
// SPLIT cluster barrier: arrive right after mbarrier init, wait only just
// before the first cross-CTA push — the barrier latency and CTA launch skew
// are hidden behind phase 1 (v-compute, STS, warp reductions).
// Partial exchange and final combine are push-style st.async + mbarrier.
// Phase 2 register-caches its anchor column before the mbarrier wait;
// post-wait dot uses 4-way ILP accumulators. (Otherwise identical to the
// best-measured R13 kernel.)
// ---------------------------------------------------------------------------

#define GB      32
#define GP      1024
#define SCOLS   128            // columns per slice (8 slices per half)

// ---------------- tiny PTX helpers ----------------
__device__ __forceinline__ uint32_t smem_u32(const void* p) {
    uint32_t a;
    asm("{ .reg .u64 t; cvta.to.shared.u64 t, %1; cvt.u32.u64 %0, t; }"
        : "=r"(a) : "l"(p));
    return a;
}
__device__ __forceinline__ uint32_t mapa_rank(uint32_t smem_addr, uint32_t rank) {
    uint32_t r;
    asm("mapa.shared::cluster.u32 %0, %1, %2;" : "=r"(r) : "r"(smem_addr), "r"(rank));
    return r;
}
__device__ __forceinline__ void mbar_init(uint32_t mbar, uint32_t count) {
    asm volatile("mbarrier.init.shared.b64 [%0], %1;" :: "r"(mbar), "r"(count) : "memory");
}
__device__ __forceinline__ void mbar_expect_tx(uint32_t mbar, uint32_t bytes) {
    asm volatile("mbarrier.arrive.expect_tx.shared.b64 _, [%0], %1;"
                 :: "r"(mbar), "r"(bytes) : "memory");
}
__device__ __forceinline__ void mbar_wait(uint32_t mbar, uint32_t parity) {
    uint32_t done;
    asm volatile(
        "{\n\t.reg .pred p;\n\t"
        "mbarrier.try_wait.parity.acquire.cta.shared::cta.b64 p, [%1], %2;\n\t"
        "selp.b32 %0, 1, 0, p;\n\t}"
        : "=r"(done) : "r"(mbar), "r"(parity) : "memory");
    if (!done) {
        asm volatile(
            "{\n\t.reg .pred P1;\n\t"
            "WL_%=:\n\t"
            "mbarrier.try_wait.parity.acquire.cta.shared::cta.b64 P1, [%0], %1, 0x989680;\n\t"
            "@P1 bra.uni WD_%=;\n\t"
            "bra.uni WL_%=;\n\t"
            "WD_%=:\n\t}"
            :: "r"(mbar), "r"(parity) : "memory");
    }
}
__device__ __forceinline__ void st_async_b64(uint32_t dst, float a, float b, uint32_t mbar) {
    float2 v = make_float2(a, b);
    unsigned long long bits = *reinterpret_cast<unsigned long long*>(&v);
    asm volatile("st.async.shared::cluster.mbarrier::complete_tx::bytes.b64 [%0], %1, [%2];"
                 :: "r"(dst), "l"(bits), "r"(mbar) : "memory");
}
__device__ __forceinline__ void st_async_b32(uint32_t dst, float a, uint32_t mbar) {
    asm volatile("st.async.shared::cluster.mbarrier::complete_tx::bytes.b32 [%0], %1, [%2];"
                 :: "r"(dst), "r"(__float_as_uint(a)), "r"(mbar) : "memory");
}
// warp-wide sum via shfl butterfly (result in all lanes)
__device__ __forceinline__ float warp_sum(float v) {
    #pragma unroll
    for (int off = 16; off; off >>= 1)
        v += __shfl_xor_sync(0xffffffff, v, off);
    return v;
}

// ---------------------------------------------------------------------------

__global__ void __launch_bounds__(512, 1) __cluster_dims__(8, 1, 1)
gcs_loss_kernel(const float* __restrict__ pred,
                const float* __restrict__ truth,
                float* __restrict__ out)
{
    __shared__ float  sv[2 * GB * SCOLS];      // 32 KB: [half][row][col]
    __shared__ float2 s_pX[8][GB];             // pushed (rowsumX, sqX) per src rank/row
    __shared__ float2 s_pY[8][GB];             // pushed (rowsumY, sqY)
    __shared__ float  s_tail[64];              // rank0: per (rank, phase2-warp) sums
    __shared__ __align__(8) unsigned long long mbar1;   // partials exchange
    __shared__ __align__(8) unsigned long long mbar2;   // final combine (rank0)

    const int slice = blockIdx.x;      // 0..7, rank within the single cluster
    const int tid   = threadIdx.x;     // 0..511
    const int wid   = tid >> 5;        // warp w loads rows 2w, 2w+1
    const int lane  = tid & 31;

    const uint32_t mbar1_a = smem_u32(&mbar1);
    const uint32_t mbar2_a = smem_u32(&mbar2);

    // ---- issue ALL global loads first (latency hidden behind init + phase 1)
    const int r0 = 2 * wid, r1 = 2 * wid + 1;
    const float* p0 = pred  + r0 * (2 * GP) + slice * SCOLS;
    const float* t0 = truth + r0 * (2 * GP) + slice * SCOLS;
    const float* p1 = pred  + r1 * (2 * GP) + slice * SCOLS;
    const float* t1 = truth + r1 * (2 * GP) + slice * SCOLS;
    float4 pX0 = ((const float4*)p0)[lane];
    float4 tX0 = ((const float4*)t0)[lane];
    float4 pY0 = ((const float4*)(p0 + GP))[lane];
    float4 tY0 = ((const float4*)(t0 + GP))[lane];
    float4 pX1 = ((const float4*)p1)[lane];
    float4 tX1 = ((const float4*)t1)[lane];
    float4 pY1 = ((const float4*)(p1 + GP))[lane];
    float4 tY1 = ((const float4*)(t1 + GP))[lane];

    // ---- mbarrier init while loads are in flight ---------------------------
    if (tid == 0) {
        mbar_init(mbar1_a, 1);
        mbar_expect_tx(mbar1_a, 8 * GB * 16);   // 8 ranks x 32 rows x (X+Y) x 8 B
        if (slice == 0) {
            mbar_init(mbar2_a, 1);
            mbar_expect_tx(mbar2_a, 64 * 4);    // 8 ranks x 8 warps x 4 B
        }
    }

    // ---- cluster barrier ARRIVE only — hide the wait behind phase 1 --------
    asm volatile("barrier.cluster.arrive.aligned;" ::: "memory");

    // ---- Phase 1 (local only): v = p - t, stash slices, warp reductions ----
    float4 vX0, vY0, vX1, vY1;
    vX0.x = pX0.x - tX0.x; vX0.y = pX0.y - tX0.y; vX0.z = pX0.z - tX0.z; vX0.w = pX0.w - tX0.w;
    vY0.x = pY0.x - tY0.x; vY0.y = pY0.y - tY0.y; vY0.z = pY0.z - tY0.z; vY0.w = pY0.w - tY0.w;
    vX1.x = pX1.x - tX1.x; vX1.y = pX1.y - tX1.y; vX1.z = pX1.z - tX1.z; vX1.w = pX1.w - tX1.w;
    vY1.x = pY1.x - tY1.x; vY1.y = pY1.y - tY1.y; vY1.z = pY1.z - tY1.z; vY1.w = pY1.w - tY1.w;
    ((float4*)(sv + r0 * SCOLS))[lane]              = vX0;
    ((float4*)(sv + GB * SCOLS + r0 * SCOLS))[lane] = vY0;
    ((float4*)(sv + r1 * SCOLS))[lane]              = vX1;
    ((float4*)(sv + GB * SCOLS + r1 * SCOLS))[lane] = vY1;

    // 8 independent warp reductions — ILP hides shfl latency
    float rsX0 = (vX0.x + vX0.y) + (vX0.z + vX0.w);
    float sqX0 = vX0.x*vX0.x + vX0.y*vX0.y + vX0.z*vX0.z + vX0.w*vX0.w;
    float rsY0 = (vY0.x + vY0.y) + (vY0.z + vY0.w);
    float sqY0 = vY0.x*vY0.x + vY0.y*vY0.y + vY0.z*vY0.z + vY0.w*vY0.w;
    float rsX1 = (vX1.x + vX1.y) + (vX1.z + vX1.w);
    float sqX1 = vX1.x*vX1.x + vX1.y*vX1.y + vX1.z*vX1.z + vX1.w*vX1.w;
    float rsY1 = (vY1.x + vY1.y) + (vY1.z + vY1.w);
    float sqY1 = vY1.x*vY1.x + vY1.y*vY1.y + vY1.z*vY1.z + vY1.w*vY1.w;
    #pragma unroll
    for (int off = 16; off; off >>= 1) {
        rsX0 += __shfl_xor_sync(0xffffffff, rsX0, off);
        sqX0 += __shfl_xor_sync(0xffffffff, sqX0, off);
        rsY0 += __shfl_xor_sync(0xffffffff, rsY0, off);
        sqY0 += __shfl_xor_sync(0xffffffff, sqY0, off);
        rsX1 += __shfl_xor_sync(0xffffffff, rsX1, off);
        sqX1 += __shfl_xor_sync(0xffffffff, sqX1, off);
        rsY1 += __shfl_xor_sync(0xffffffff, rsY1, off);
        sqY1 += __shfl_xor_sync(0xffffffff, sqY1, off);
    }

    // ---- cluster barrier WAIT: peers' mbarriers now guaranteed initialized -
    asm volatile("barrier.cluster.wait.aligned;" ::: "memory");

    // push both rows' partials to ALL 8 ranks, fanned across all 32 lanes
    {
        const int r = lane & 7;                  // destination rank
        const int which = lane >> 3;             // 0: Xr0, 1: Yr0, 2: Xr1, 3: Yr1
        const uint32_t mb = mapa_rank(mbar1_a, r);
        uint32_t slot; float a, b;
        switch (which) {
            case 0:  slot = smem_u32(&s_pX[slice][r0]); a = rsX0; b = sqX0; break;
            case 1:  slot = smem_u32(&s_pY[slice][r0]); a = rsY0; b = sqY0; break;
            case 2:  slot = smem_u32(&s_pX[slice][r1]); a = rsX1; b = sqX1; break;
            default: slot = smem_u32(&s_pY[slice][r1]); a = rsY1; b = sqY1; break;
        }
        st_async_b64(mapa_rank(slot, r), a, b, mb);
    }
    __syncthreads();     // sv fully written (needed by phase 2)

    // ---- Phase 2: fully warp-autonomous, warps 0..7 ------------------------
    if (wid < 8) {
        const int h = wid >> 2;                 // warps 0-3: X, 4-7: Y
        const int i = (wid & 3) * 32 + lane;    // anchor column within slice
        const float* svh = sv + h * GB * SCOLS;

        // register-cache the anchor column + colsq BEFORE the mbar wait (2-way ILP)
        float vcol[GB];
        float cs0 = 0.f, cs1 = 0.f;
        #pragma unroll
        for (int b = 0; b < GB; b += 2) {
            vcol[b]     = svh[b * SCOLS + i];
            vcol[b + 1] = svh[(b + 1) * SCOLS + i];
            cs0 += vcol[b] * vcol[b];
            cs1 += vcol[b + 1] * vcol[b + 1];
        }
        float colsq = cs0 + cs1;

        // wait for partials; lane l rebuilds rowsum/sumsq of row l
        mbar_wait(mbar1_a, 0);
        const float2* part = (h == 0) ? &s_pX[0][0] : &s_pY[0][0];
        float rowsum_l = 0.f, sq_l = 0.f;
        #pragma unroll
        for (int s = 0; s < 8; s++) {
            float2 m = part[s * GB + lane];
            rowsum_l += m.x;
            sq_l     += m.y;
        }
        float S2 = warp_sum(sq_l);

        // dot via register broadcast of rowsums — 4 independent FFMA chains
        float d0 = 0.f, d1 = 0.f, d2 = 0.f, d3 = 0.f;
        #pragma unroll
        for (int b = 0; b < GB; b += 4) {
            d0 += vcol[b]     * __shfl_sync(0xffffffff, rowsum_l, b);
            d1 += vcol[b + 1] * __shfl_sync(0xffffffff, rowsum_l, b + 1);
            d2 += vcol[b + 2] * __shfl_sync(0xffffffff, rowsum_l, b + 2);
            d3 += vcol[b + 3] * __shfl_sync(0xffffffff, rowsum_l, b + 3);
        }
        float dot = (d0 + d1) + (d2 + d3);

        float s   = S2 - 2.0f * dot + (float)GP * colsq;
        float val = warp_sum(sqrtf(fmaxf(s, 0.0f)));

        // push warp sum straight to rank0
        if (lane == 0) {
            st_async_b32(mapa_rank(smem_u32(&s_tail[slice * 8 + wid]), 0), val,
                         mapa_rank(mbar2_a, 0));
        }

        // rank0 warp0: cooperative final combine
        if (slice == 0 && wid == 0) {
            mbar_wait(mbar2_a, 0);
            float t = s_tail[lane] + s_tail[lane + 32];
            t = warp_sum(t);
            if (lane == 0)
                *out = t * (1.0f / (float)(GB * 2));
        }
    }
    // no trailing barrier: all cross-CTA traffic is push-style; every rank's
    // inbound st.asyncs are acknowledged by that rank's own mbar waits.
}

extern "C" void kernel_launch(void* const* d_in, const int* in_sizes, int n_in,
                              void* d_out, int out_size)
{
    (void)in_sizes; (void)n_in; (void)out_size;
    const float* pred  = (const float*)d_in[0];
    const float* truth = (const float*)d_in[1];
    float* out = (float*)d_out;

    gcs_loss_kernel<<<8, 512>>>(pred, truth, out);
}

// round 16
// speedup vs baseline: 1.3397x; 1.3397x over previous
#include <cuda_runtime.h>
#include <cstdint>

// ---------------------------------------------------------------------------
// Gcs_loss, expanded form:
//   v = pred - truth, halves X = v[:,:P], Y = v[:,P:]
//   s_i = S2 - 2 * dot_i + P * colsq_i,
//   dot_i = sum_b v[b,i]*rowsum[b],  colsq_i = sum_b v[b,i]^2
//   out = ( sum_i sqrt(s_i^X) + sum_i sqrt(s_i^Y) ) / (2B),  B=32, P=1024.
//
// ONE cluster of 8 CTAs, 512 threads (16 warps). HALF-SPECIALIZED:
//   CTAs 0-3 own X, CTAs 4-7 own Y; each CTA owns 256 columns of its half.
// Partials are exchanged only within the 4-CTA half-group (each CTA's wait
// depends on 4 CTAs, not 8). Warp w loads rows 2w, 2w+1 of its 256-col
// slice. Single cluster.sync overlapped with the global loads; exchange and
// final combine are push-style st.async + mbarrier. Phase 2 register-caches
// its anchor column before the mbarrier wait; dot uses 4-way ILP. Ordering
// identical to the best-measured R13 kernel.
// ---------------------------------------------------------------------------

#define GB      32
#define GP      1024
#define SCOLS   256            // columns per CTA (4 slices per half)

// ---------------- tiny PTX helpers ----------------
__device__ __forceinline__ uint32_t smem_u32(const void* p) {
    uint32_t a;
    asm("{ .reg .u64 t; cvta.to.shared.u64 t, %1; cvt.u32.u64 %0, t; }"
        : "=r"(a) : "l"(p));
    return a;
}
__device__ __forceinline__ uint32_t mapa_rank(uint32_t smem_addr, uint32_t rank) {
    uint32_t r;
    asm("mapa.shared::cluster.u32 %0, %1, %2;" : "=r"(r) : "r"(smem_addr), "r"(rank));
    return r;
}
__device__ __forceinline__ void mbar_init(uint32_t mbar, uint32_t count) {
    asm volatile("mbarrier.init.shared.b64 [%0], %1;" :: "r"(mbar), "r"(count) : "memory");
}
__device__ __forceinline__ void mbar_expect_tx(uint32_t mbar, uint32_t bytes) {
    asm volatile("mbarrier.arrive.expect_tx.shared.b64 _, [%0], %1;"
                 :: "r"(mbar), "r"(bytes) : "memory");
}
__device__ __forceinline__ void mbar_wait(uint32_t mbar, uint32_t parity) {
    uint32_t done;
    asm volatile(
        "{\n\t.reg .pred p;\n\t"
        "mbarrier.try_wait.parity.acquire.cta.shared::cta.b64 p, [%1], %2;\n\t"
        "selp.b32 %0, 1, 0, p;\n\t}"
        : "=r"(done) : "r"(mbar), "r"(parity) : "memory");
    if (!done) {
        asm volatile(
            "{\n\t.reg .pred P1;\n\t"
            "WL_%=:\n\t"
            "mbarrier.try_wait.parity.acquire.cta.shared::cta.b64 P1, [%0], %1, 0x989680;\n\t"
            "@P1 bra.uni WD_%=;\n\t"
            "bra.uni WL_%=;\n\t"
            "WD_%=:\n\t}"
            :: "r"(mbar), "r"(parity) : "memory");
    }
}
__device__ __forceinline__ void st_async_b64(uint32_t dst, float a, float b, uint32_t mbar) {
    float2 v = make_float2(a, b);
    unsigned long long bits = *reinterpret_cast<unsigned long long*>(&v);
    asm volatile("st.async.shared::cluster.mbarrier::complete_tx::bytes.b64 [%0], %1, [%2];"
                 :: "r"(dst), "l"(bits), "r"(mbar) : "memory");
}
__device__ __forceinline__ void st_async_b32(uint32_t dst, float a, uint32_t mbar) {
    asm volatile("st.async.shared::cluster.mbarrier::complete_tx::bytes.b32 [%0], %1, [%2];"
                 :: "r"(dst), "r"(__float_as_uint(a)), "r"(mbar) : "memory");
}
// warp-wide sum via shfl butterfly (result in all lanes)
__device__ __forceinline__ float warp_sum(float v) {
    #pragma unroll
    for (int off = 16; off; off >>= 1)
        v += __shfl_xor_sync(0xffffffff, v, off);
    return v;
}

// ---------------------------------------------------------------------------

__global__ void __launch_bounds__(512, 1) __cluster_dims__(8, 1, 1)
gcs_loss_kernel(const float* __restrict__ pred,
                const float* __restrict__ truth,
                float* __restrict__ out)
{
    __shared__ float  sv[GB * SCOLS];          // 32 KB: [row][col] (my half only)
    __shared__ float2 s_p[4][GB];              // pushed (rowsum, sq) per group rank/row
    __shared__ float  s_tail[64];              // rank0: per (rank, phase2-warp) sums
    __shared__ __align__(8) unsigned long long mbar1;   // partials exchange (group)
    __shared__ __align__(8) unsigned long long mbar2;   // final combine (rank0)

    const int slice = blockIdx.x;      // 0..7
    const int half  = slice >> 2;      // 0 = X (CTAs 0-3), 1 = Y (CTAs 4-7)
    const int sub   = slice & 3;       // 256-col slice within the half
    const int gbase = half << 2;       // first rank of my half-group
    const int tid   = threadIdx.x;     // 0..511
    const int wid   = tid >> 5;        // warp w loads rows 2w, 2w+1
    const int lane  = tid & 31;

    const uint32_t mbar1_a = smem_u32(&mbar1);
    const uint32_t mbar2_a = smem_u32(&mbar2);

    // ---- issue ALL global loads first (latency hidden behind init + sync) --
    const int r0 = 2 * wid, r1 = 2 * wid + 1;
    const int cbase = half * GP + sub * SCOLS;           // column base in 2P row
    const float* p0 = pred  + r0 * (2 * GP) + cbase;
    const float* t0 = truth + r0 * (2 * GP) + cbase;
    const float* p1 = pred  + r1 * (2 * GP) + cbase;
    const float* t1 = truth + r1 * (2 * GP) + cbase;
    float4 pA0 = ((const float4*)p0)[lane];
    float4 pB0 = ((const float4*)p0)[lane + 32];
    float4 tA0 = ((const float4*)t0)[lane];
    float4 tB0 = ((const float4*)t0)[lane + 32];
    float4 pA1 = ((const float4*)p1)[lane];
    float4 pB1 = ((const float4*)p1)[lane + 32];
    float4 tA1 = ((const float4*)t1)[lane];
    float4 tB1 = ((const float4*)t1)[lane + 32];

    // ---- mbarrier init while loads are in flight ---------------------------
    if (tid == 0) {
        mbar_init(mbar1_a, 1);
        mbar_expect_tx(mbar1_a, 4 * GB * 8);    // 4 group ranks x 32 rows x 8 B
        if (slice == 0) {
            mbar_init(mbar2_a, 1);
            mbar_expect_tx(mbar2_a, 64 * 4);    // 8 ranks x 8 warps x 4 B
        }
    }

    // single cluster barrier: mbarriers visible before any st.async
    asm volatile("barrier.cluster.arrive.aligned;" ::: "memory");
    asm volatile("barrier.cluster.wait.aligned;"   ::: "memory");

    // ---- Phase 1: v = p - t, stash slices, per-row reductions --------------
    float4 vA0, vB0, vA1, vB1;
    vA0.x = pA0.x - tA0.x; vA0.y = pA0.y - tA0.y; vA0.z = pA0.z - tA0.z; vA0.w = pA0.w - tA0.w;
    vB0.x = pB0.x - tB0.x; vB0.y = pB0.y - tB0.y; vB0.z = pB0.z - tB0.z; vB0.w = pB0.w - tB0.w;
    vA1.x = pA1.x - tA1.x; vA1.y = pA1.y - tA1.y; vA1.z = pA1.z - tA1.z; vA1.w = pA1.w - tA1.w;
    vB1.x = pB1.x - tB1.x; vB1.y = pB1.y - tB1.y; vB1.z = pB1.z - tB1.z; vB1.w = pB1.w - tB1.w;
    ((float4*)(sv + r0 * SCOLS))[lane]      = vA0;
    ((float4*)(sv + r0 * SCOLS))[lane + 32] = vB0;
    ((float4*)(sv + r1 * SCOLS))[lane]      = vA1;
    ((float4*)(sv + r1 * SCOLS))[lane + 32] = vB1;

    // 4 independent warp reductions — ILP hides shfl latency
    float rs0 = (vA0.x + vA0.y) + (vA0.z + vA0.w) + (vB0.x + vB0.y) + (vB0.z + vB0.w);
    float sq0 = vA0.x*vA0.x + vA0.y*vA0.y + vA0.z*vA0.z + vA0.w*vA0.w
              + vB0.x*vB0.x + vB0.y*vB0.y + vB0.z*vB0.z + vB0.w*vB0.w;
    float rs1 = (vA1.x + vA1.y) + (vA1.z + vA1.w) + (vB1.x + vB1.y) + (vB1.z + vB1.w);
    float sq1 = vA1.x*vA1.x + vA1.y*vA1.y + vA1.z*vA1.z + vA1.w*vA1.w
              + vB1.x*vB1.x + vB1.y*vB1.y + vB1.z*vB1.z + vB1.w*vB1.w;
    #pragma unroll
    for (int off = 16; off; off >>= 1) {
        rs0 += __shfl_xor_sync(0xffffffff, rs0, off);
        sq0 += __shfl_xor_sync(0xffffffff, sq0, off);
        rs1 += __shfl_xor_sync(0xffffffff, rs1, off);
        sq1 += __shfl_xor_sync(0xffffffff, sq1, off);
    }

    // push both rows' partials to my 4-CTA half-group, fanned across 8 lanes
    if (lane < 8) {
        const int r = gbase + (lane & 3);        // destination rank (my group)
        const int row = (lane >> 2) ? r1 : r0;   // lanes 0-3: r0, lanes 4-7: r1
        const float a = (lane >> 2) ? rs1 : rs0;
        const float b = (lane >> 2) ? sq1 : sq0;
        const uint32_t slot = smem_u32(&s_p[sub][row]);
        st_async_b64(mapa_rank(slot, r), a, b, mapa_rank(mbar1_a, r));
    }
    __syncthreads();     // sv fully written (needed by phase 2)

    // ---- Phase 2: fully warp-autonomous, warps 0..7 ------------------------
    if (wid < 8) {
        const int i = wid * 32 + lane;          // anchor column within my slice
        // register-cache the anchor column + colsq BEFORE the mbar wait (2-way ILP)
        float vcol[GB];
        float cs0 = 0.f, cs1 = 0.f;
        #pragma unroll
        for (int b = 0; b < GB; b += 2) {
            vcol[b]     = sv[b * SCOLS + i];
            vcol[b + 1] = sv[(b + 1) * SCOLS + i];
            cs0 += vcol[b] * vcol[b];
            cs1 += vcol[b + 1] * vcol[b + 1];
        }
        float colsq = cs0 + cs1;

        // wait for group partials; lane l rebuilds rowsum/sumsq of row l
        mbar_wait(mbar1_a, 0);
        float rowsum_l = 0.f, sq_l = 0.f;
        #pragma unroll
        for (int s = 0; s < 4; s++) {
            float2 m = s_p[s][lane];
            rowsum_l += m.x;
            sq_l     += m.y;
        }
        float S2 = warp_sum(sq_l);

        // dot via register broadcast of rowsums — 4 independent FFMA chains
        float d0 = 0.f, d1 = 0.f, d2 = 0.f, d3 = 0.f;
        #pragma unroll
        for (int b = 0; b < GB; b += 4) {
            d0 += vcol[b]     * __shfl_sync(0xffffffff, rowsum_l, b);
            d1 += vcol[b + 1] * __shfl_sync(0xffffffff, rowsum_l, b + 1);
            d2 += vcol[b + 2] * __shfl_sync(0xffffffff, rowsum_l, b + 2);
            d3 += vcol[b + 3] * __shfl_sync(0xffffffff, rowsum_l, b + 3);
        }
        float dot = (d0 + d1) + (d2 + d3);

        float s   = S2 - 2.0f * dot + (float)GP * colsq;
        float val = warp_sum(sqrtf(fmaxf(s, 0.0f)));

        // push warp sum straight to rank0
        if (lane == 0) {
            st_async_b32(mapa_rank(smem_u32(&s_tail[slice * 8 + wid]), 0), val,
                         mapa_rank(mbar2_a, 0));
        }

        // rank0 warp0: cooperative final combine
        if (slice == 0 && wid == 0) {
            mbar_wait(mbar2_a, 0);
            float t = s_tail[lane] + s_tail[lane + 32];
            t = warp_sum(t);
            if (lane == 0)
                *out = t * (1.0f / (float)(GB * 2));
        }
    }
    // no trailing barrier: all cross-CTA traffic is push-style; every rank's
    // inbound st.asyncs are acknowledged by that rank's own mbar waits.
}

extern "C" void kernel_launch(void* const* d_in, const int* in_sizes, int n_in,
                              void* d_out, int out_size)
{
    (void)in_sizes; (void)n_in; (void)out_size;
    const float* pred  = (const float*)d_in[0];
    const float* truth = (const float*)d_in[1];
    float* out = (float*)d_out;

    gcs_loss_kernel<<<8, 512>>>(pred, truth, out);
}

// round 17
// speedup vs baseline: 1.3462x; 1.0048x over previous
#include <cuda_runtime.h>
#include <cstdint>

// ---------------------------------------------------------------------------
// Gcs_loss, expanded form:
//   v = pred - truth, halves X = v[:,:P], Y = v[:,P:]
//   s_i = S2 - 2 * dot_i + P * colsq_i
//   out = ( sum_i sqrt(s_i^X) + sum_i sqrt(s_i^Y) ) / (2B),  B=32, P=1024.
//
// ONE cluster of 8 CTAs, 512 threads (16 warps). HALF-SPECIALIZED:
//   CTAs 0-3 own X, CTAs 4-7 own Y; each CTA owns 256 columns of its half.
// Partials exchanged only within the 4-CTA half-group. Phase 2 uses ALL 16
// warps: each warp covers 16 anchors, with lanes 0-15 / 16-31 splitting the
// 32-row b-loop and combining via shfl_xor(16). Single cluster.sync
// overlapped with loads; push-style st.async + mbarrier everywhere.
// ---------------------------------------------------------------------------

#define GB      32
#define GP      1024
#define SCOLS   256            // columns per CTA (4 slices per half)

// ---------------- tiny PTX helpers ----------------
__device__ __forceinline__ uint32_t smem_u32(const void* p) {
    uint32_t a;
    asm("{ .reg .u64 t; cvta.to.shared.u64 t, %1; cvt.u32.u64 %0, t; }"
        : "=r"(a) : "l"(p));
    return a;
}
__device__ __forceinline__ uint32_t mapa_rank(uint32_t smem_addr, uint32_t rank) {
    uint32_t r;
    asm("mapa.shared::cluster.u32 %0, %1, %2;" : "=r"(r) : "r"(smem_addr), "r"(rank));
    return r;
}
__device__ __forceinline__ void mbar_init(uint32_t mbar, uint32_t count) {
    asm volatile("mbarrier.init.shared.b64 [%0], %1;" :: "r"(mbar), "r"(count) : "memory");
}
__device__ __forceinline__ void mbar_expect_tx(uint32_t mbar, uint32_t bytes) {
    asm volatile("mbarrier.arrive.expect_tx.shared.b64 _, [%0], %1;"
                 :: "r"(mbar), "r"(bytes) : "memory");
}
__device__ __forceinline__ void mbar_wait(uint32_t mbar, uint32_t parity) {
    uint32_t done;
    asm volatile(
        "{\n\t.reg .pred p;\n\t"
        "mbarrier.try_wait.parity.acquire.cta.shared::cta.b64 p, [%1], %2;\n\t"
        "selp.b32 %0, 1, 0, p;\n\t}"
        : "=r"(done) : "r"(mbar), "r"(parity) : "memory");
    if (!done) {
        asm volatile(
            "{\n\t.reg .pred P1;\n\t"
            "WL_%=:\n\t"
            "mbarrier.try_wait.parity.acquire.cta.shared::cta.b64 P1, [%0], %1, 0x989680;\n\t"
            "@P1 bra.uni WD_%=;\n\t"
            "bra.uni WL_%=;\n\t"
            "WD_%=:\n\t}"
            :: "r"(mbar), "r"(parity) : "memory");
    }
}
__device__ __forceinline__ void st_async_b64(uint32_t dst, float a, float b, uint32_t mbar) {
    float2 v = make_float2(a, b);
    unsigned long long bits = *reinterpret_cast<unsigned long long*>(&v);
    asm volatile("st.async.shared::cluster.mbarrier::complete_tx::bytes.b64 [%0], %1, [%2];"
                 :: "r"(dst), "l"(bits), "r"(mbar) : "memory");
}
__device__ __forceinline__ void st_async_b32(uint32_t dst, float a, uint32_t mbar) {
    asm volatile("st.async.shared::cluster.mbarrier::complete_tx::bytes.b32 [%0], %1, [%2];"
                 :: "r"(dst), "r"(__float_as_uint(a)), "r"(mbar) : "memory");
}
// warp-wide sum via shfl butterfly (result in all lanes)
__device__ __forceinline__ float warp_sum(float v) {
    #pragma unroll
    for (int off = 16; off; off >>= 1)
        v += __shfl_xor_sync(0xffffffff, v, off);
    return v;
}

// ---------------------------------------------------------------------------

__global__ void __launch_bounds__(512, 1) __cluster_dims__(8, 1, 1)
gcs_loss_kernel(const float* __restrict__ pred,
                const float* __restrict__ truth,
                float* __restrict__ out)
{
    __shared__ float  sv[GB * SCOLS];          // 32 KB: [row][col] (my half only)
    __shared__ float2 s_p[4][GB];              // pushed (rowsum, sq) per group rank/row
    __shared__ float  s_tail[128];             // rank0: per (rank, warp) sums
    __shared__ __align__(8) unsigned long long mbar1;   // partials exchange (group)
    __shared__ __align__(8) unsigned long long mbar2;   // final combine (rank0)

    const int slice = blockIdx.x;      // 0..7
    const int half  = slice >> 2;      // 0 = X (CTAs 0-3), 1 = Y (CTAs 4-7)
    const int sub   = slice & 3;       // 256-col slice within the half
    const int gbase = half << 2;       // first rank of my half-group
    const int tid   = threadIdx.x;     // 0..511
    const int wid   = tid >> 5;        // warp w loads rows 2w, 2w+1
    const int lane  = tid & 31;

    const uint32_t mbar1_a = smem_u32(&mbar1);
    const uint32_t mbar2_a = smem_u32(&mbar2);

    // ---- issue ALL global loads first (latency hidden behind init + sync) --
    const int r0 = 2 * wid, r1 = 2 * wid + 1;
    const int cbase = half * GP + sub * SCOLS;           // column base in 2P row
    const float* p0 = pred  + r0 * (2 * GP) + cbase;
    const float* t0 = truth + r0 * (2 * GP) + cbase;
    const float* p1 = pred  + r1 * (2 * GP) + cbase;
    const float* t1 = truth + r1 * (2 * GP) + cbase;
    float4 pA0 = ((const float4*)p0)[lane];
    float4 pB0 = ((const float4*)p0)[lane + 32];
    float4 tA0 = ((const float4*)t0)[lane];
    float4 tB0 = ((const float4*)t0)[lane + 32];
    float4 pA1 = ((const float4*)p1)[lane];
    float4 pB1 = ((const float4*)p1)[lane + 32];
    float4 tA1 = ((const float4*)t1)[lane];
    float4 tB1 = ((const float4*)t1)[lane + 32];

    // ---- mbarrier init while loads are in flight ---------------------------
    if (tid == 0) {
        mbar_init(mbar1_a, 1);
        mbar_expect_tx(mbar1_a, 4 * GB * 8);    // 4 group ranks x 32 rows x 8 B
        if (slice == 0) {
            mbar_init(mbar2_a, 1);
            mbar_expect_tx(mbar2_a, 128 * 4);   // 8 ranks x 16 warps x 4 B
        }
    }

    // single cluster barrier: mbarriers visible before any st.async
    asm volatile("barrier.cluster.arrive.aligned;" ::: "memory");
    asm volatile("barrier.cluster.wait.aligned;"   ::: "memory");

    // ---- Phase 1: v = p - t, stash slices, per-row reductions --------------
    float4 vA0, vB0, vA1, vB1;
    vA0.x = pA0.x - tA0.x; vA0.y = pA0.y - tA0.y; vA0.z = pA0.z - tA0.z; vA0.w = pA0.w - tA0.w;
    vB0.x = pB0.x - tB0.x; vB0.y = pB0.y - tB0.y; vB0.z = pB0.z - tB0.z; vB0.w = pB0.w - tB0.w;
    vA1.x = pA1.x - tA1.x; vA1.y = pA1.y - tA1.y; vA1.z = pA1.z - tA1.z; vA1.w = pA1.w - tA1.w;
    vB1.x = pB1.x - tB1.x; vB1.y = pB1.y - tB1.y; vB1.z = pB1.z - tB1.z; vB1.w = pB1.w - tB1.w;
    ((float4*)(sv + r0 * SCOLS))[lane]      = vA0;
    ((float4*)(sv + r0 * SCOLS))[lane + 32] = vB0;
    ((float4*)(sv + r1 * SCOLS))[lane]      = vA1;
    ((float4*)(sv + r1 * SCOLS))[lane + 32] = vB1;

    // 4 independent warp reductions — ILP hides shfl latency
    float rs0 = (vA0.x + vA0.y) + (vA0.z + vA0.w) + (vB0.x + vB0.y) + (vB0.z + vB0.w);
    float sq0 = vA0.x*vA0.x + vA0.y*vA0.y + vA0.z*vA0.z + vA0.w*vA0.w
              + vB0.x*vB0.x + vB0.y*vB0.y + vB0.z*vB0.z + vB0.w*vB0.w;
    float rs1 = (vA1.x + vA1.y) + (vA1.z + vA1.w) + (vB1.x + vB1.y) + (vB1.z + vB1.w);
    float sq1 = vA1.x*vA1.x + vA1.y*vA1.y + vA1.z*vA1.z + vA1.w*vA1.w
              + vB1.x*vB1.x + vB1.y*vB1.y + vB1.z*vB1.z + vB1.w*vB1.w;
    #pragma unroll
    for (int off = 16; off; off >>= 1) {
        rs0 += __shfl_xor_sync(0xffffffff, rs0, off);
        sq0 += __shfl_xor_sync(0xffffffff, sq0, off);
        rs1 += __shfl_xor_sync(0xffffffff, rs1, off);
        sq1 += __shfl_xor_sync(0xffffffff, sq1, off);
    }

    // push both rows' partials to my 4-CTA half-group, fanned across 8 lanes
    if (lane < 8) {
        const int r = gbase + (lane & 3);        // destination rank (my group)
        const int row = (lane >> 2) ? r1 : r0;   // lanes 0-3: r0, lanes 4-7: r1
        const float a = (lane >> 2) ? rs1 : rs0;
        const float b = (lane >> 2) ? sq1 : sq0;
        const uint32_t slot = smem_u32(&s_p[sub][row]);
        st_async_b64(mapa_rank(slot, r), a, b, mapa_rank(mbar1_a, r));
    }
    __syncthreads();     // sv fully written (needed by phase 2)

    // ---- Phase 2: ALL 16 warps; each warp = 16 anchors, b split 16/16 ------
    {
        const int hb = lane & 16;               // my 16-row b-half (0 or 16)
        const int i  = wid * 16 + (lane & 15);  // anchor column within my slice

        // register-cache my 16-row anchor sub-column + colsq BEFORE the wait
        float vcol[16];
        float cs0 = 0.f, cs1 = 0.f;
        #pragma unroll
        for (int k = 0; k < 16; k += 2) {
            vcol[k]     = sv[(hb + k) * SCOLS + i];
            vcol[k + 1] = sv[(hb + k + 1) * SCOLS + i];
            cs0 += vcol[k] * vcol[k];
            cs1 += vcol[k + 1] * vcol[k + 1];
        }
        float colsq = cs0 + cs1;

        // wait for group partials; lane l rebuilds rowsum/sumsq of row l
        mbar_wait(mbar1_a, 0);
        float rowsum_l = 0.f, sq_l = 0.f;
        #pragma unroll
        for (int s = 0; s < 4; s++) {
            float2 m = s_p[s][lane];
            rowsum_l += m.x;
            sq_l     += m.y;
        }
        float S2 = warp_sum(sq_l);

        // partial dot over my 16 rows — 4 independent FFMA chains
        float d0 = 0.f, d1 = 0.f, d2 = 0.f, d3 = 0.f;
        #pragma unroll
        for (int k = 0; k < 16; k += 4) {
            d0 += vcol[k]     * __shfl_sync(0xffffffff, rowsum_l, hb + k);
            d1 += vcol[k + 1] * __shfl_sync(0xffffffff, rowsum_l, hb + k + 1);
            d2 += vcol[k + 2] * __shfl_sync(0xffffffff, rowsum_l, hb + k + 2);
            d3 += vcol[k + 3] * __shfl_sync(0xffffffff, rowsum_l, hb + k + 3);
        }
        float part = (float)GP * colsq - 2.0f * ((d0 + d1) + (d2 + d3));

        // combine the two b-halves of each anchor, add S2, sqrt
        part += __shfl_xor_sync(0xffffffff, part, 16);
        float val = sqrtf(fmaxf(S2 + part, 0.0f));
        // each anchor now appears in 2 lanes -> warp_sum double-counts;
        // compensated by the final 1/128 scale.
        val = warp_sum(val);

        // push warp sum straight to rank0
        if (lane == 0) {
            st_async_b32(mapa_rank(smem_u32(&s_tail[slice * 16 + wid]), 0), val,
                         mapa_rank(mbar2_a, 0));
        }

        // rank0 warp0: cooperative final combine (128 values, x2-counted)
        if (slice == 0 && wid == 0) {
            mbar_wait(mbar2_a, 0);
            float t = (s_tail[lane] + s_tail[lane + 32])
                    + (s_tail[lane + 64] + s_tail[lane + 96]);
            t = warp_sum(t);
            if (lane == 0)
                *out = t * (1.0f / (float)(GB * 2 * 2));   // extra /2: dual-lane anchors
        }
    }
    // no trailing barrier: all cross-CTA traffic is push-style; every rank's
    // inbound st.asyncs are acknowledged by that rank's own mbar waits.
}

extern "C" void kernel_launch(void* const* d_in, const int* in_sizes, int n_in,
                              void* d_out, int out_size)
{
    (void)in_sizes; (void)n_in; (void)out_size;
    const float* pred  = (const float*)d_in[0];
    const float* truth = (const float*)d_in[1];
    float* out = (float*)d_out;

    gcs_loss_kernel<<<8, 512>>>(pred, truth, out);
}